// round 5
// baseline (speedup 1.0000x reference)
#include <cuda_runtime.h>

// DenseWarpLayer: bilinear warp, N=8, H=512, W=512, C=32 fp32.
// R5: R4's proven structure (8 threads/pixel, full-128B-line warp loads,
// 32 regs / 8 blocks / 64 warps per SM) extended from 2 to 4 sequential
// pixels per thread with ALL flow loads hoisted. Amortizes the serial
// flow->gather latency chain: 750 exposed cyc/pixel vs R4's 900.
// Streaming stores keep the write-once output from evicting the image
// row-reuse window in L2.

#define N_ 8
#define H_ 512
#define W_ 512
#define C4_ 8u            // 32 channels = 8 float4
#define ROW4 (W_ * C4_)   // float4 per image row = 4096
#define PPT 4u            // pixels per thread

__device__ __forceinline__ unsigned gather_base(unsigned pix, unsigned c4,
                                                const float2 fl,
                                                float& ax, float& ay)
{
    const unsigned w = pix & (W_ - 1);
    const unsigned h = (pix >> 9) & (H_ - 1);
    const unsigned n = pix >> 18;

    const float qy = (float)h - fl.x;
    const float qx = (float)w - fl.y;

    float fyf = floorf(qy);
    float fxf = floorf(qx);
    fyf = fminf(fmaxf(fyf, 0.0f), (float)(H_ - 2));
    fxf = fminf(fmaxf(fxf, 0.0f), (float)(W_ - 2));

    ay = fminf(fmaxf(qy - fyf, 0.0f), 1.0f);
    ax = fminf(fmaxf(qx - fxf, 0.0f), 1.0f);

    return ((n * H_ + (unsigned)(int)fyf) * W_ + (unsigned)(int)fxf) * C4_ + c4;
}

__device__ __forceinline__ float4 bilerp4(const float4 tl, const float4 tr,
                                          const float4 bl, const float4 br,
                                          const float ax, const float ay)
{
    float4 r; float top, bot;
    top = tl.x + ax * (tr.x - tl.x); bot = bl.x + ax * (br.x - bl.x);
    r.x = top + ay * (bot - top);
    top = tl.y + ax * (tr.y - tl.y); bot = bl.y + ax * (br.y - bl.y);
    r.y = top + ay * (bot - top);
    top = tl.z + ax * (tr.z - tl.z); bot = bl.z + ax * (br.z - bl.z);
    r.z = top + ay * (bot - top);
    top = tl.w + ax * (tr.w - tl.w); bot = bl.w + ax * (br.w - bl.w);
    r.w = top + ay * (bot - top);
    return r;
}

__device__ __forceinline__ void do_pixel(const float4* __restrict__ img4,
                                         float4* __restrict__ out4,
                                         unsigned pix, unsigned c4,
                                         const float2 fl)
{
    float ax, ay;
    const unsigned rb = gather_base(pix, c4, fl, ax, ay);

    const float4 tl = __ldg(img4 + rb);
    const float4 tr = __ldg(img4 + rb + C4_);
    const float4 bl = __ldg(img4 + rb + ROW4);
    const float4 br = __ldg(img4 + rb + ROW4 + C4_);

    __stcs(out4 + pix * C4_ + c4, bilerp4(tl, tr, bl, br, ax, ay));
}

__global__ __launch_bounds__(256, 8)
void dense_warp_kernel(const float* __restrict__ image,
                       const float* __restrict__ flow,
                       float* __restrict__ out)
{
    // threads = N*H*W*8/PPT = 4,194,304; warp = 4 pixel-slots x 8 quads.
    // Iteration i covers 4 consecutive pixels [g*16 + i*4 .. +3] so every
    // warp-level LDG.128/STG.128 still touches 4 full 128B lines.
    const unsigned tid  = blockIdx.x * 256u + threadIdx.x;
    const unsigned c4   = tid & 7u;
    const unsigned slot = tid >> 3;                 // 0 .. 2,097,151... (pair count)
    const unsigned grp  = slot >> 2;
    const unsigned r    = slot & 3u;
    const unsigned pix0 = grp * (PPT * 4u) + r;     // pixels pix0, +4, +8, +12

    // hoist all PPT flow loads: later pixels' flow latency hides under
    // earlier pixels' gather/compute
    const float2* fl2 = reinterpret_cast<const float2*>(flow);
    const float2 fl0 = __ldg(fl2 + pix0);
    const float2 fl1 = __ldg(fl2 + pix0 + 4u);
    const float2 fl2v = __ldg(fl2 + pix0 + 8u);
    const float2 fl3 = __ldg(fl2 + pix0 + 12u);

    const float4* img4 = reinterpret_cast<const float4*>(image);
    float4* out4 = reinterpret_cast<float4*>(out);

    do_pixel(img4, out4, pix0,       c4, fl0);
    do_pixel(img4, out4, pix0 + 4u,  c4, fl1);
    do_pixel(img4, out4, pix0 + 8u,  c4, fl2v);
    do_pixel(img4, out4, pix0 + 12u, c4, fl3);
}

extern "C" void kernel_launch(void* const* d_in, const int* in_sizes, int n_in,
                              void* d_out, int out_size)
{
    const float* image = (const float*)d_in[0];
    const float* flow  = (const float*)d_in[1];
    float* out = (float*)d_out;

    // 4,194,304 threads / 256 = 16,384 blocks
    dense_warp_kernel<<<16384, 256>>>(image, flow, out);
}